// round 1
// baseline (speedup 1.0000x reference)
#include <cuda_runtime.h>
#include <math.h>

// Problem constants (fixed by the dataset)
constexpr int NN = 50000;   // nodes
constexpr int HH = 16;      // hidden
constexpr int RR = 32;      // relations
constexpr int CC = 8;       // classes
constexpr int RN = RR * NN; // segments

// Scratch (device globals: no allocation allowed)
__device__ float g_inv[RN];       // 1/max(cnt,1) per (rel,dst) segment
__device__ int   g_cnt[RN];       // edge counts per segment
__device__ float g_x[NN * HH];    // layer-1 node features

// ---------------------------------------------------------------------------
// 0) zero scratch + output
__global__ void k_init(float* __restrict__ out) {
    int i = blockIdx.x * blockDim.x + threadIdx.x;
    if (i < RN)      g_cnt[i] = 0;
    if (i < NN * HH) g_x[i]   = 0.0f;
    if (i < NN * CC) out[i]   = 0.0f;
}

// 1) count edges per (rel,dst) segment
__global__ void k_count(const int* __restrict__ et, const int* __restrict__ dst, int E) {
    int e = blockIdx.x * blockDim.x + threadIdx.x;
    if (e >= E) return;
    atomicAdd(&g_cnt[et[e] * NN + dst[e]], 1);
}

// 2) reciprocal counts
__global__ void k_inv() {
    int i = blockIdx.x * blockDim.x + threadIdx.x;
    if (i >= RN) return;
    int c = g_cnt[i];
    g_inv[i] = 1.0f / (float)(c > 0 ? c : 1);
}

// 3) layer-1 scatter: x[d] += inv[r,d] * w1[r,s]   (4 threads per edge, float4 each)
__global__ void k_l1(const int* __restrict__ et, const int* __restrict__ srcv,
                     const int* __restrict__ dstv, const float* __restrict__ w1, int E) {
    int idx = blockIdx.x * blockDim.x + threadIdx.x;
    int e = idx >> 2, q = idx & 3;
    if (e >= E) return;
    int r = et[e], s = srcv[e], d = dstv[e];
    float inv = __ldg(&g_inv[r * NN + d]);
    const float4 w = __ldg(((const float4*)(w1 + (long)(r * NN + s) * HH)) + q);
    float4 m = make_float4(w.x * inv, w.y * inv, w.z * inv, w.w * inv);
    float* p = &g_x[d * HH + q * 4];
    asm volatile("red.global.add.v4.f32 [%0], {%1,%2,%3,%4};"
                 :: "l"(p), "f"(m.x), "f"(m.y), "f"(m.z), "f"(m.w) : "memory");
}

// 4) x = relu(x + root1 + b1)
__global__ void k_relu(const float* __restrict__ root1, const float* __restrict__ b1) {
    int i = blockIdx.x * blockDim.x + threadIdx.x;
    if (i >= NN * HH) return;
    float v = g_x[i] + root1[i] + b1[i & (HH - 1)];
    g_x[i] = v > 0.0f ? v : 0.0f;
}

// 5) layer-2 scatter: out[d] += inv[r,d] * (x[s] @ w2[r])   (2 threads per edge)
__global__ void k_l2(const int* __restrict__ et, const int* __restrict__ srcv,
                     const int* __restrict__ dstv, const float* __restrict__ w2,
                     float* __restrict__ out, int E) {
    __shared__ float s_w2[RR * HH * CC];   // 16 KB
    for (int i = threadIdx.x; i < RR * HH * CC; i += blockDim.x) s_w2[i] = w2[i];
    __syncthreads();

    int idx = blockIdx.x * blockDim.x + threadIdx.x;
    int e = idx >> 1, half = idx & 1;
    if (e >= E) return;
    int r = et[e], s = srcv[e], d = dstv[e];
    float inv = __ldg(&g_inv[r * NN + d]);

    const float4* xr = (const float4*)(g_x + s * HH);
    const float*  wr = s_w2 + r * HH * CC + half * 4;

    float4 acc = make_float4(0.f, 0.f, 0.f, 0.f);
#pragma unroll
    for (int h4 = 0; h4 < 4; h4++) {
        float4 xv = __ldg(xr + h4);
        float xs[4] = {xv.x, xv.y, xv.z, xv.w};
#pragma unroll
        for (int j = 0; j < 4; j++) {
            const float* wrow = wr + (h4 * 4 + j) * CC;
            acc.x += xs[j] * wrow[0];
            acc.y += xs[j] * wrow[1];
            acc.z += xs[j] * wrow[2];
            acc.w += xs[j] * wrow[3];
        }
    }
    acc.x *= inv; acc.y *= inv; acc.z *= inv; acc.w *= inv;
    float* p = out + d * CC + half * 4;
    asm volatile("red.global.add.v4.f32 [%0], {%1,%2,%3,%4};"
                 :: "l"(p), "f"(acc.x), "f"(acc.y), "f"(acc.z), "f"(acc.w) : "memory");
}

// 6) finalize: out = log_softmax(out + x @ root2 + b2)
__global__ void k_fin(const float* __restrict__ root2, const float* __restrict__ b2,
                      float* __restrict__ out) {
    __shared__ float s_r2[HH * CC];
    __shared__ float s_b2[CC];
    for (int i = threadIdx.x; i < HH * CC; i += blockDim.x) s_r2[i] = root2[i];
    if (threadIdx.x < CC) s_b2[threadIdx.x] = b2[threadIdx.x];
    __syncthreads();

    int n = blockIdx.x * blockDim.x + threadIdx.x;
    if (n >= NN) return;

    float y[CC];
    float4 a0 = *(const float4*)(out + n * CC);
    float4 a1 = *(const float4*)(out + n * CC + 4);
    y[0] = a0.x; y[1] = a0.y; y[2] = a0.z; y[3] = a0.w;
    y[4] = a1.x; y[5] = a1.y; y[6] = a1.z; y[7] = a1.w;

#pragma unroll
    for (int h = 0; h < HH; h++) {
        float xv = g_x[n * HH + h];
#pragma unroll
        for (int c = 0; c < CC; c++) y[c] += xv * s_r2[h * CC + c];
    }
#pragma unroll
    for (int c = 0; c < CC; c++) y[c] += s_b2[c];

    float m = y[0];
#pragma unroll
    for (int c = 1; c < CC; c++) m = fmaxf(m, y[c]);
    float sum = 0.0f;
#pragma unroll
    for (int c = 0; c < CC; c++) sum += __expf(y[c] - m);
    float l = m + logf(sum);
#pragma unroll
    for (int c = 0; c < CC; c++) out[n * CC + c] = y[c] - l;
}

// ---------------------------------------------------------------------------
extern "C" void kernel_launch(void* const* d_in, const int* in_sizes, int n_in,
                              void* d_out, int out_size) {
    const int*   ei    = (const int*)d_in[0];     // [2, E]
    const int*   et    = (const int*)d_in[1];     // [E]
    const float* w1    = (const float*)d_in[2];   // [R, N, H]
    const float* root1 = (const float*)d_in[3];   // [N, H]
    const float* b1    = (const float*)d_in[4];   // [H]
    const float* w2    = (const float*)d_in[5];   // [R, H, C]
    const float* root2 = (const float*)d_in[6];   // [H, C]
    const float* b2    = (const float*)d_in[7];   // [C]
    float* out = (float*)d_out;

    const int E = in_sizes[0] / 2;
    const int* srcv = ei;
    const int* dstv = ei + E;

    const int T = 256;
    k_init <<<(RN + T - 1) / T, T>>> (out);
    k_count<<<(E + T - 1) / T, T>>> (et, dstv, E);
    k_inv  <<<(RN + T - 1) / T, T>>> ();
    k_l1   <<<(4 * E + T - 1) / T, T>>> (et, srcv, dstv, w1, E);
    k_relu <<<(NN * HH + T - 1) / T, T>>> (root1, b1);
    k_l2   <<<(2 * E + T - 1) / T, T>>> (et, srcv, dstv, w2, out, E);
    k_fin  <<<(NN + T - 1) / T, T>>> (root2, b2, out);
}

// round 4
// speedup vs baseline: 1.0436x; 1.0436x over previous
#include <cuda_runtime.h>
#include <math.h>

constexpr int NN = 50000;   // nodes
constexpr int HH = 16;      // hidden
constexpr int RR = 32;      // relations
constexpr int CC = 8;       // classes
constexpr int RN = RR * NN; // segments
constexpr int EMAX = 1600000;

// Scratch (device globals: no allocation allowed)
__device__ int                g_cnt[RN];     // edge counts per (rel,dst)
__device__ float              g_x[NN * HH];  // layer-1 node features
__device__ unsigned long long g_pk[EMAX];    // packed edges: s | d<<16 | r<<32

// ---------------------------------------------------------------------------
// 0) zero scratch + output
__global__ void k_init(float* __restrict__ out) {
    int i = blockIdx.x * blockDim.x + threadIdx.x;
    if (i < RN)      g_cnt[i] = 0;
    if (i < NN * HH) g_x[i]   = 0.0f;
    if (i < NN * CC) out[i]   = 0.0f;
}

// 1) pack edges + count per-(rel,dst) segment (fused)
__global__ void k_pack(const int* __restrict__ et, const int* __restrict__ srcv,
                       const int* __restrict__ dstv, int E) {
    int e = blockIdx.x * blockDim.x + threadIdx.x;
    if (e >= E) return;
    int r = et[e], s = srcv[e], d = dstv[e];
    g_pk[e] = (unsigned long long)(unsigned)s
            | ((unsigned long long)(unsigned)d << 16)
            | ((unsigned long long)(unsigned)r << 32);
    atomicAdd(&g_cnt[r * NN + d], 1);
}

// 2) layer-1 scatter: x[d] += (1/cnt[r,d]) * w1[r,s]  (4 threads/edge, float4 each)
__global__ void k_l1(const float* __restrict__ w1, int E) {
    int idx = blockIdx.x * blockDim.x + threadIdx.x;
    int e = idx >> 2, q = idx & 3;
    if (e >= E) return;
    unsigned long long p = g_pk[e];
    int s = (int)(p & 0xFFFFu);
    int d = (int)((p >> 16) & 0xFFFFu);
    int r = (int)(p >> 32);
    int c = __ldg(&g_cnt[r * NN + d]);
    float inv = 1.0f / (float)(c > 0 ? c : 1);
    const float4 w = __ldg(((const float4*)(w1 + ((long)(r * NN + s) << 4))) + q);
    float* pd = &g_x[d * HH + q * 4];
    asm volatile("red.global.add.v4.f32 [%0], {%1,%2,%3,%4};"
                 :: "l"(pd), "f"(w.x * inv), "f"(w.y * inv),
                    "f"(w.z * inv), "f"(w.w * inv) : "memory");
}

// 3) x = relu(x + root1 + b1)
__global__ void k_relu(const float* __restrict__ root1, const float* __restrict__ b1) {
    int i = blockIdx.x * blockDim.x + threadIdx.x;
    if (i >= NN * HH) return;
    float v = g_x[i] + root1[i] + b1[i & (HH - 1)];
    g_x[i] = v > 0.0f ? v : 0.0f;
}

// 4) layer-2 scatter: out[d] += (1/cnt[r,d]) * (x[s] @ w2[r])  (2 threads/edge, grid-stride)
__global__ void k_l2(const float* __restrict__ w2, float* __restrict__ out, int E) {
    __shared__ float s_w2[RR * HH * CC];   // 16 KB
    for (int i = threadIdx.x; i < RR * HH * CC; i += blockDim.x) s_w2[i] = w2[i];
    __syncthreads();

    int total = 2 * E;
    int stride = gridDim.x * blockDim.x;
    for (int idx = blockIdx.x * blockDim.x + threadIdx.x; idx < total; idx += stride) {
        int e = idx >> 1, half = idx & 1;
        unsigned long long p = g_pk[e];
        int s = (int)(p & 0xFFFFu);
        int d = (int)((p >> 16) & 0xFFFFu);
        int r = (int)(p >> 32);
        int c = __ldg(&g_cnt[r * NN + d]);
        float inv = 1.0f / (float)(c > 0 ? c : 1);

        const float4* xr = (const float4*)(g_x + s * HH);
        const float*  wr = s_w2 + r * HH * CC + half * 4;

        float4 acc = make_float4(0.f, 0.f, 0.f, 0.f);
#pragma unroll
        for (int h4 = 0; h4 < 4; h4++) {
            float4 xv = __ldg(xr + h4);
            float xs[4] = {xv.x, xv.y, xv.z, xv.w};
#pragma unroll
            for (int j = 0; j < 4; j++) {
                const float* wrow = wr + (h4 * 4 + j) * CC;
                acc.x += xs[j] * wrow[0];
                acc.y += xs[j] * wrow[1];
                acc.z += xs[j] * wrow[2];
                acc.w += xs[j] * wrow[3];
            }
        }
        float* pd = out + d * CC + half * 4;
        asm volatile("red.global.add.v4.f32 [%0], {%1,%2,%3,%4};"
                     :: "l"(pd), "f"(acc.x * inv), "f"(acc.y * inv),
                        "f"(acc.z * inv), "f"(acc.w * inv) : "memory");
    }
}

// 5) finalize: out = log_softmax(out + x @ root2 + b2)
__global__ void k_fin(const float* __restrict__ root2, const float* __restrict__ b2,
                      float* __restrict__ out) {
    __shared__ float s_r2[HH * CC];
    __shared__ float s_b2[CC];
    for (int i = threadIdx.x; i < HH * CC; i += blockDim.x) s_r2[i] = root2[i];
    if (threadIdx.x < CC) s_b2[threadIdx.x] = b2[threadIdx.x];
    __syncthreads();

    int n = blockIdx.x * blockDim.x + threadIdx.x;
    if (n >= NN) return;

    float y[CC];
    float4 a0 = *(const float4*)(out + n * CC);
    float4 a1 = *(const float4*)(out + n * CC + 4);
    y[0] = a0.x; y[1] = a0.y; y[2] = a0.z; y[3] = a0.w;
    y[4] = a1.x; y[5] = a1.y; y[6] = a1.z; y[7] = a1.w;

#pragma unroll
    for (int h = 0; h < HH; h++) {
        float xv = g_x[n * HH + h];
#pragma unroll
        for (int c = 0; c < CC; c++) y[c] += xv * s_r2[h * CC + c];
    }
#pragma unroll
    for (int c = 0; c < CC; c++) y[c] += s_b2[c];

    float m = y[0];
#pragma unroll
    for (int c = 1; c < CC; c++) m = fmaxf(m, y[c]);
    float sum = 0.0f;
#pragma unroll
    for (int c = 0; c < CC; c++) sum += __expf(y[c] - m);
    float l = m + logf(sum);
#pragma unroll
    for (int c = 0; c < CC; c++) out[n * CC + c] = y[c] - l;
}

// ---------------------------------------------------------------------------
extern "C" void kernel_launch(void* const* d_in, const int* in_sizes, int n_in,
                              void* d_out, int out_size) {
    const int*   ei    = (const int*)d_in[0];     // [2, E]
    const int*   et    = (const int*)d_in[1];     // [E]
    const float* w1    = (const float*)d_in[2];   // [R, N, H]
    const float* root1 = (const float*)d_in[3];   // [N, H]
    const float* b1    = (const float*)d_in[4];   // [H]
    const float* w2    = (const float*)d_in[5];   // [R, H, C]
    const float* root2 = (const float*)d_in[6];   // [H, C]
    const float* b2    = (const float*)d_in[7];   // [C]
    float* out = (float*)d_out;

    const int E = in_sizes[0] / 2;
    const int* srcv = ei;
    const int* dstv = ei + E;

    const int T = 256;
    k_init <<<(RN + T - 1) / T, T>>> (out);
    k_pack <<<(E + T - 1) / T, T>>> (et, srcv, dstv, E);
    k_l1   <<<(4 * E + T - 1) / T, T>>> (w1, E);
    k_relu <<<(NN * HH + T - 1) / T, T>>> (root1, b1);
    k_l2   <<<888, T>>> (w2, out, E);
    k_fin  <<<(NN + T - 1) / T, T>>> (root2, b2, out);
}

// round 8
// speedup vs baseline: 1.3151x; 1.2602x over previous
#include <cuda_runtime.h>
#include <math.h>

constexpr int NN = 50000;   // nodes
constexpr int HH = 16;      // hidden
constexpr int RR = 32;      // relations
constexpr int CC = 8;       // classes
constexpr int RN = RR * NN; // segments
constexpr int EMAX = 1600000;

// Scratch (device globals: no allocation allowed)
__device__ int                g_cnt[RN];     // edge counts per (rel,dst)
__device__ float              g_x[NN * HH];  // layer-1 node features
__device__ unsigned long long g_pk[EMAX];    // packed edges (sorted by rel): s | d<<16 | r<<32
__device__ int                g_hist[RR];    // global relation histogram
__device__ int                g_cursor[RR];  // scatter cursors (= exclusive scan of hist)

// ---------------------------------------------------------------------------
// 0) zero scratch + output
__global__ void k_init(float* __restrict__ out) {
    int i = blockIdx.x * blockDim.x + threadIdx.x;
    if (i < RN)      g_cnt[i] = 0;
    if (i < NN * HH) g_x[i]   = 0.0f;
    if (i < NN * CC) out[i]   = 0.0f;
    if (i < RR)      g_hist[i] = 0;
}

// 1) relation histogram + (rel,dst) segment counts (fused)
__global__ void k_hist(const int* __restrict__ et, const int* __restrict__ dstv, int E) {
    __shared__ int sh[RR];
    if (threadIdx.x < RR) sh[threadIdx.x] = 0;
    __syncthreads();
    int e = blockIdx.x * blockDim.x + threadIdx.x;
    if (e < E) {
        int r = et[e], d = dstv[e];
        atomicAdd(&sh[r], 1);
        atomicAdd(&g_cnt[r * NN + d], 1);
    }
    __syncthreads();
    if (threadIdx.x < RR) {
        int v = sh[threadIdx.x];
        if (v) atomicAdd(&g_hist[threadIdx.x], v);
    }
}

// 2) exclusive scan of 32-bin histogram -> cursors
__global__ void k_scan() {
    __shared__ int s[RR];
    int t = threadIdx.x;
    s[t] = g_hist[t];
    __syncthreads();
    if (t == 0) {
        int acc = 0;
        for (int i = 0; i < RR; i++) { int v = s[i]; s[i] = acc; acc += v; }
    }
    __syncthreads();
    g_cursor[t] = s[t];
}

// 3) scatter edges into relation-sorted packed array
__global__ void k_scatter(const int* __restrict__ et, const int* __restrict__ srcv,
                          const int* __restrict__ dstv, int E) {
    __shared__ int sh[RR];     // per-block bin sizes / ranks
    __shared__ int sbase[RR];  // per-block bin bases
    int t = threadIdx.x;
    if (t < RR) sh[t] = 0;
    __syncthreads();
    int e = blockIdx.x * blockDim.x + t;
    int r = 0, s = 0, d = 0, rank = 0;
    bool ok = e < E;
    if (ok) {
        r = et[e]; s = srcv[e]; d = dstv[e];
        rank = atomicAdd(&sh[r], 1);
    }
    __syncthreads();
    if (t < RR) sbase[t] = sh[t] ? atomicAdd(&g_cursor[t], sh[t]) : 0;
    __syncthreads();
    if (ok) {
        g_pk[sbase[r] + rank] = (unsigned long long)(unsigned)s
                              | ((unsigned long long)(unsigned)d << 16)
                              | ((unsigned long long)(unsigned)r << 32);
    }
}

// 4) layer-1 scatter: x[d] += (1/cnt[r,d]) * w1[r,s]  (4 threads/edge, float4 each)
__global__ void k_l1(const float* __restrict__ w1, int E) {
    int idx = blockIdx.x * blockDim.x + threadIdx.x;
    int e = idx >> 2, q = idx & 3;
    if (e >= E) return;
    unsigned long long p = g_pk[e];
    int s = (int)(p & 0xFFFFu);
    int d = (int)((p >> 16) & 0xFFFFu);
    int r = (int)(p >> 32);
    int c = __ldg(&g_cnt[r * NN + d]);
    float inv = 1.0f / (float)(c > 0 ? c : 1);
    const float4 w = __ldg(((const float4*)(w1 + ((long)(r * NN + s) << 4))) + q);
    float* pd = &g_x[d * HH + q * 4];
    asm volatile("red.global.add.v4.f32 [%0], {%1,%2,%3,%4};"
                 :: "l"(pd), "f"(w.x * inv), "f"(w.y * inv),
                    "f"(w.z * inv), "f"(w.w * inv) : "memory");
}

// 5) x = relu(x + root1 + b1)  (float4)
__global__ void k_relu(const float4* __restrict__ root1, const float* __restrict__ b1) {
    int i = blockIdx.x * blockDim.x + threadIdx.x;
    if (i >= NN * HH / 4) return;
    float4 v = ((float4*)g_x)[i];
    float4 rr = __ldg(root1 + i);
    int q = (i & 3) * 4;
    v.x += rr.x + b1[q];
    v.y += rr.y + b1[q + 1];
    v.z += rr.z + b1[q + 2];
    v.w += rr.w + b1[q + 3];
    v.x = fmaxf(v.x, 0.f); v.y = fmaxf(v.y, 0.f);
    v.z = fmaxf(v.z, 0.f); v.w = fmaxf(v.w, 0.f);
    ((float4*)g_x)[i] = v;
}

// 6) layer-2 scatter: out[d] += (1/cnt[r,d]) * (x[s] @ w2[r])
//    1 thread/edge; r-sorted edges -> warp-uniform r -> broadcast smem reads
__global__ void k_l2(const float* __restrict__ w2, float* __restrict__ out, int E) {
    __shared__ float s_w2[RR * HH * CC];   // 16 KB
    for (int i = threadIdx.x; i < RR * HH * CC; i += blockDim.x) s_w2[i] = w2[i];
    __syncthreads();

    int stride = gridDim.x * blockDim.x;
    for (int e = blockIdx.x * blockDim.x + threadIdx.x; e < E; e += stride) {
        unsigned long long p = g_pk[e];
        int s = (int)(p & 0xFFFFu);
        int d = (int)((p >> 16) & 0xFFFFu);
        int r = (int)(p >> 32);
        int c0 = __ldg(&g_cnt[r * NN + d]);
        float inv = 1.0f / (float)(c0 > 0 ? c0 : 1);

        const float4* xr = (const float4*)(g_x + s * HH);
        float4 x0 = __ldg(xr), x1 = __ldg(xr + 1), x2 = __ldg(xr + 2), x3 = __ldg(xr + 3);
        float xs[16] = {x0.x, x0.y, x0.z, x0.w, x1.x, x1.y, x1.z, x1.w,
                        x2.x, x2.y, x2.z, x2.w, x3.x, x3.y, x3.z, x3.w};

        const float* wr = s_w2 + r * HH * CC;
        float y[CC] = {0.f, 0.f, 0.f, 0.f, 0.f, 0.f, 0.f, 0.f};
#pragma unroll
        for (int h = 0; h < HH; h++) {
            float xv = xs[h];
#pragma unroll
            for (int c = 0; c < CC; c++) y[c] += xv * wr[h * CC + c];
        }
        float* pd = out + d * CC;
        asm volatile("red.global.add.v4.f32 [%0], {%1,%2,%3,%4};"
                     :: "l"(pd), "f"(y[0] * inv), "f"(y[1] * inv),
                        "f"(y[2] * inv), "f"(y[3] * inv) : "memory");
        asm volatile("red.global.add.v4.f32 [%0], {%1,%2,%3,%4};"
                     :: "l"(pd + 4), "f"(y[4] * inv), "f"(y[5] * inv),
                        "f"(y[6] * inv), "f"(y[7] * inv) : "memory");
    }
}

// 7) finalize: out = log_softmax(out + x @ root2 + b2)
__global__ void k_fin(const float* __restrict__ root2, const float* __restrict__ b2,
                      float* __restrict__ out) {
    __shared__ float s_r2[HH * CC];
    __shared__ float s_b2[CC];
    for (int i = threadIdx.x; i < HH * CC; i += blockDim.x) s_r2[i] = root2[i];
    if (threadIdx.x < CC) s_b2[threadIdx.x] = b2[threadIdx.x];
    __syncthreads();

    int n = blockIdx.x * blockDim.x + threadIdx.x;
    if (n >= NN) return;

    float y[CC];
    float4 a0 = *(const float4*)(out + n * CC);
    float4 a1 = *(const float4*)(out + n * CC + 4);
    y[0] = a0.x; y[1] = a0.y; y[2] = a0.z; y[3] = a0.w;
    y[4] = a1.x; y[5] = a1.y; y[6] = a1.z; y[7] = a1.w;

#pragma unroll
    for (int h = 0; h < HH; h++) {
        float xv = g_x[n * HH + h];
#pragma unroll
        for (int c = 0; c < CC; c++) y[c] += xv * s_r2[h * CC + c];
    }
#pragma unroll
    for (int c = 0; c < CC; c++) y[c] += s_b2[c];

    float m = y[0];
#pragma unroll
    for (int c = 1; c < CC; c++) m = fmaxf(m, y[c]);
    float sum = 0.0f;
#pragma unroll
    for (int c = 0; c < CC; c++) sum += __expf(y[c] - m);
    float l = m + logf(sum);
#pragma unroll
    for (int c = 0; c < CC; c++) out[n * CC + c] = y[c] - l;
}

// ---------------------------------------------------------------------------
extern "C" void kernel_launch(void* const* d_in, const int* in_sizes, int n_in,
                              void* d_out, int out_size) {
    const int*   ei    = (const int*)d_in[0];     // [2, E]
    const int*   et    = (const int*)d_in[1];     // [E]
    const float* w1    = (const float*)d_in[2];   // [R, N, H]
    const float* root1 = (const float*)d_in[3];   // [N, H]
    const float* b1    = (const float*)d_in[4];   // [H]
    const float* w2    = (const float*)d_in[5];   // [R, H, C]
    const float* root2 = (const float*)d_in[6];   // [H, C]
    const float* b2    = (const float*)d_in[7];   // [C]
    float* out = (float*)d_out;

    const int E = in_sizes[0] / 2;
    const int* srcv = ei;
    const int* dstv = ei + E;

    const int T = 256;
    k_init    <<<(RN + T - 1) / T, T>>> (out);
    k_hist    <<<(E + T - 1) / T, T>>> (et, dstv, E);
    k_scan    <<<1, RR>>> ();
    k_scatter <<<(E + T - 1) / T, T>>> (et, srcv, dstv, E);
    k_l1      <<<(4 * E + T - 1) / T, T>>> (w1, E);
    k_relu    <<<(NN * HH / 4 + T - 1) / T, T>>> ((const float4*)root1, b1);
    k_l2      <<<888, T>>> (w2, out, E);
    k_fin     <<<(NN + T - 1) / T, T>>> (root2, b2, out);
}

// round 9
// speedup vs baseline: 1.3948x; 1.0606x over previous
#include <cuda_runtime.h>
#include <math.h>

constexpr int NN = 50000;   // nodes
constexpr int HH = 16;      // hidden
constexpr int RR = 32;      // relations
constexpr int CC = 8;       // classes
constexpr int RN = RR * NN; // segments
constexpr int EMAX = 1600000;

// Scratch (device globals: no allocation allowed)
__device__ int                g_cnt[RN];     // edge counts per (rel,dst)
__device__ float              g_x[NN * HH];  // layer-1 node features
__device__ unsigned long long g_pk[EMAX];    // packed edges (sorted by rel): s | d<<16 | r<<32
__device__ int                g_hist[RR];    // global relation histogram (zeroed by k_scan)
__device__ int                g_cursor[RR];  // scatter cursors (= exclusive scan of hist)

// ---------------------------------------------------------------------------
// 0) zero scratch + output, fused with relation histogram over et
__global__ void k_init_hist(const int* __restrict__ et, float* __restrict__ out, int E) {
    __shared__ int sh[RR];
    int t = threadIdx.x;
    if (t < RR) sh[t] = 0;
    __syncthreads();
    int i = blockIdx.x * blockDim.x + t;
    if (i < RN)      g_cnt[i] = 0;
    if (i < NN * HH) g_x[i]   = 0.0f;
    if (i < NN * CC) out[i]   = 0.0f;
    if (i < E)       atomicAdd(&sh[et[i]], 1);
    __syncthreads();
    if (t < RR) {
        int v = sh[t];
        if (v) atomicAdd(&g_hist[t], v);
    }
}

// 1) exclusive scan of 32-bin histogram -> cursors; re-zero g_hist for next replay
__global__ void k_scan() {
    __shared__ int s[RR];
    int t = threadIdx.x;
    s[t] = g_hist[t];
    __syncthreads();
    if (t == 0) {
        int acc = 0;
        for (int i = 0; i < RR; i++) { int v = s[i]; s[i] = acc; acc += v; }
    }
    __syncthreads();
    g_cursor[t] = s[t];
    g_hist[t] = 0;
}

// 2) scatter edges into relation-sorted packed array (warp-aggregated ranks)
//    + fused (rel,dst) segment counting
__global__ void k_scatter(const int* __restrict__ et, const int* __restrict__ srcv,
                          const int* __restrict__ dstv, int E) {
    __shared__ int sh[RR];     // per-block bin sizes / ranks
    __shared__ int sbase[RR];  // per-block bin bases
    int t = threadIdx.x;
    if (t < RR) sh[t] = 0;
    __syncthreads();

    int e = blockIdx.x * blockDim.x + t;
    bool ok = e < E;
    int r = ok ? et[e] : RR;               // RR = dummy bin for tail lanes
    int s = 0, d = 0;
    if (ok) { s = srcv[e]; d = dstv[e]; }

    // warp-aggregated rank within block bin
    unsigned m = __match_any_sync(0xffffffffu, r);
    int lane = t & 31;
    int leader = __ffs(m) - 1;
    int pre = __popc(m & ((1u << lane) - 1));
    int base = 0;
    if (lane == leader && r < RR) base = atomicAdd(&sh[r], __popc(m));
    base = __shfl_sync(0xffffffffu, base, leader);
    int rank = base + pre;

    __syncthreads();
    if (t < RR) sbase[t] = sh[t] ? atomicAdd(&g_cursor[t], sh[t]) : 0;
    __syncthreads();

    if (ok) {
        g_pk[sbase[r] + rank] = (unsigned long long)(unsigned)s
                              | ((unsigned long long)(unsigned)d << 16)
                              | ((unsigned long long)(unsigned)r << 32);
        atomicAdd(&g_cnt[r * NN + d], 1);
    }
}

// 3) layer-1 scatter: x[d] += (1/cnt[r,d]) * w1[r,s]  (4 threads/edge, float4 each)
__global__ void k_l1(const float* __restrict__ w1, int E) {
    int idx = blockIdx.x * blockDim.x + threadIdx.x;
    int e = idx >> 2, q = idx & 3;
    if (e >= E) return;
    unsigned long long p = g_pk[e];
    int s = (int)(p & 0xFFFFu);
    int d = (int)((p >> 16) & 0xFFFFu);
    int r = (int)(p >> 32);
    int c = __ldg(&g_cnt[r * NN + d]);          // >= 1 by construction
    float inv = __fdividef(1.0f, (float)c);
    const float4 w = __ldg(((const float4*)(w1 + ((long)(r * NN + s) << 4))) + q);
    float* pd = &g_x[d * HH + q * 4];
    asm volatile("red.global.add.v4.f32 [%0], {%1,%2,%3,%4};"
                 :: "l"(pd), "f"(w.x * inv), "f"(w.y * inv),
                    "f"(w.z * inv), "f"(w.w * inv) : "memory");
}

// 4) x = relu(x + root1 + b1)  (float4)
__global__ void k_relu(const float4* __restrict__ root1, const float* __restrict__ b1) {
    int i = blockIdx.x * blockDim.x + threadIdx.x;
    if (i >= NN * HH / 4) return;
    float4 v = ((float4*)g_x)[i];
    float4 rr = __ldg(root1 + i);
    int q = (i & 3) * 4;
    v.x += rr.x + b1[q];
    v.y += rr.y + b1[q + 1];
    v.z += rr.z + b1[q + 2];
    v.w += rr.w + b1[q + 3];
    v.x = fmaxf(v.x, 0.f); v.y = fmaxf(v.y, 0.f);
    v.z = fmaxf(v.z, 0.f); v.w = fmaxf(v.w, 0.f);
    ((float4*)g_x)[i] = v;
}

// 5) layer-2 scatter: out[d] += (1/cnt[r,d]) * (x[s] @ w2[r])
//    1 thread/edge; r-sorted edges -> warp-uniform r -> broadcast smem reads
__global__ void k_l2(const float* __restrict__ w2, float* __restrict__ out, int E) {
    __shared__ float s_w2[RR * HH * CC];   // 16 KB
    for (int i = threadIdx.x; i < RR * HH * CC; i += blockDim.x) s_w2[i] = w2[i];
    __syncthreads();

    int stride = gridDim.x * blockDim.x;
    for (int e = blockIdx.x * blockDim.x + threadIdx.x; e < E; e += stride) {
        unsigned long long p = g_pk[e];
        int s = (int)(p & 0xFFFFu);
        int d = (int)((p >> 16) & 0xFFFFu);
        int r = (int)(p >> 32);
        int c0 = __ldg(&g_cnt[r * NN + d]);
        float inv = __fdividef(1.0f, (float)c0);

        const float4* xr = (const float4*)(g_x + s * HH);
        float4 x0 = __ldg(xr), x1 = __ldg(xr + 1), x2 = __ldg(xr + 2), x3 = __ldg(xr + 3);
        float xs[16] = {x0.x, x0.y, x0.z, x0.w, x1.x, x1.y, x1.z, x1.w,
                        x2.x, x2.y, x2.z, x2.w, x3.x, x3.y, x3.z, x3.w};

        const float* wr = s_w2 + r * HH * CC;
        float y[CC] = {0.f, 0.f, 0.f, 0.f, 0.f, 0.f, 0.f, 0.f};
#pragma unroll
        for (int h = 0; h < HH; h++) {
            float xv = xs[h];
#pragma unroll
            for (int c = 0; c < CC; c++) y[c] += xv * wr[h * CC + c];
        }
        float* pd = out + d * CC;
        asm volatile("red.global.add.v4.f32 [%0], {%1,%2,%3,%4};"
                     :: "l"(pd), "f"(y[0] * inv), "f"(y[1] * inv),
                        "f"(y[2] * inv), "f"(y[3] * inv) : "memory");
        asm volatile("red.global.add.v4.f32 [%0], {%1,%2,%3,%4};"
                     :: "l"(pd + 4), "f"(y[4] * inv), "f"(y[5] * inv),
                        "f"(y[6] * inv), "f"(y[7] * inv) : "memory");
    }
}

// 6) finalize: out = log_softmax(out + x @ root2 + b2)
__global__ void k_fin(const float* __restrict__ root2, const float* __restrict__ b2,
                      float* __restrict__ out) {
    __shared__ float s_r2[HH * CC];
    __shared__ float s_b2[CC];
    for (int i = threadIdx.x; i < HH * CC; i += blockDim.x) s_r2[i] = root2[i];
    if (threadIdx.x < CC) s_b2[threadIdx.x] = b2[threadIdx.x];
    __syncthreads();

    int n = blockIdx.x * blockDim.x + threadIdx.x;
    if (n >= NN) return;

    float y[CC];
    float4 a0 = *(const float4*)(out + n * CC);
    float4 a1 = *(const float4*)(out + n * CC + 4);
    y[0] = a0.x; y[1] = a0.y; y[2] = a0.z; y[3] = a0.w;
    y[4] = a1.x; y[5] = a1.y; y[6] = a1.z; y[7] = a1.w;

#pragma unroll
    for (int h = 0; h < HH; h++) {
        float xv = g_x[n * HH + h];
#pragma unroll
        for (int c = 0; c < CC; c++) y[c] += xv * s_r2[h * CC + c];
    }
#pragma unroll
    for (int c = 0; c < CC; c++) y[c] += s_b2[c];

    float m = y[0];
#pragma unroll
    for (int c = 1; c < CC; c++) m = fmaxf(m, y[c]);
    float sum = 0.0f;
#pragma unroll
    for (int c = 0; c < CC; c++) sum += __expf(y[c] - m);
    float l = m + logf(sum);
#pragma unroll
    for (int c = 0; c < CC; c++) out[n * CC + c] = y[c] - l;
}

// ---------------------------------------------------------------------------
extern "C" void kernel_launch(void* const* d_in, const int* in_sizes, int n_in,
                              void* d_out, int out_size) {
    const int*   ei    = (const int*)d_in[0];     // [2, E]
    const int*   et    = (const int*)d_in[1];     // [E]
    const float* w1    = (const float*)d_in[2];   // [R, N, H]
    const float* root1 = (const float*)d_in[3];   // [N, H]
    const float* b1    = (const float*)d_in[4];   // [H]
    const float* w2    = (const float*)d_in[5];   // [R, H, C]
    const float* root2 = (const float*)d_in[6];   // [H, C]
    const float* b2    = (const float*)d_in[7];   // [C]
    float* out = (float*)d_out;

    const int E = in_sizes[0] / 2;
    const int* srcv = ei;
    const int* dstv = ei + E;

    const int T = 256;
    int big = (RN > E ? RN : E);
    k_init_hist <<<(big + T - 1) / T, T>>> (et, out, E);
    k_scan      <<<1, RR>>> ();
    k_scatter   <<<(E + T - 1) / T, T>>> (et, srcv, dstv, E);
    k_l1        <<<(4 * E + T - 1) / T, T>>> (w1, E);
    k_relu      <<<(NN * HH / 4 + T - 1) / T, T>>> ((const float4*)root1, b1);
    k_l2        <<<888, T>>> (w2, out, E);
    k_fin       <<<(NN + T - 1) / T, T>>> (root2, b2, out);
}